// round 6
// baseline (speedup 1.0000x reference)
#include <cuda_runtime.h>
#include <cuda_fp16.h>
#include <cstdint>
#include <cstddef>

#define HWC 9216
#define EPSN 1e-5f

// ---------------- scratch (__device__ globals; no allocation) ----------------
__device__ float g_y1[75497472];      // conv1 output [128,64,9216]
__device__ float g_logits[1179648];   // [128,9216]
__device__ float g_g2[1179648];       // gen-block intermediate [8,16,9216]
__device__ float g_tsum[512];         // sum_hw sr [8,64]
__device__ float g_T1[512];           // sum_hw tg
__device__ float g_T2[512];           // sum_hw tg^2
__device__ float g_op[8192];          // [128,64]
__device__ float g_u[8192];           // W^T opn
__device__ float g_v[8192];           // sum_hw sr*cof
__device__ float g_A1[8192];          // GN affine scale (GN1 then GN2)
__device__ float g_D1[8192];          // GN affine shift
__device__ float g_gn2s[8192];
__device__ float g_gn2q[8192];
__device__ float g_mstat[256];        // per-bn (mu, invstd) of msk
__device__ float g_in2s[128];
__device__ float g_in2q[128];
__device__ float g_in2stat[256];
__device__ float2 g_pms[4608];        // per-(bn,blk) online softmax partials (m,s)
__device__ float2 g_Ms[128];          // per-bn (M, 1/S)
__device__ __align__(16) __half g_wpack[36864];     // packed fp16 conv1 weights
__device__ __align__(16) __half g_x[75497472];      // fp16 GN1+ReLU input, [bn][chunk][hw][16slots]

// ---------------- helpers ----------------
__device__ __forceinline__ float wred(float v) {
#pragma unroll
    for (int o = 16; o > 0; o >>= 1) v += __shfl_xor_sync(0xffffffffu, v, o);
    return v;
}
__device__ __forceinline__ float bsum256(float v, float* red) {
    int t = threadIdx.x; red[t] = v; __syncthreads();
#pragma unroll
    for (int s = 128; s > 0; s >>= 1) { if (t < s) red[t] += red[t + s]; __syncthreads(); }
    float r = red[0]; __syncthreads(); return r;
}
__device__ __forceinline__ float bmax256(float v, float* red) {
    int t = threadIdx.x; red[t] = v; __syncthreads();
#pragma unroll
    for (int s = 128; s > 0; s >>= 1) { if (t < s) red[t] = fmaxf(red[t], red[t + s]); __syncthreads(); }
    float r = red[0]; __syncthreads(); return r;
}

// ---------------- 0: pack conv1 weights; zero loss accumulator ----------------
__global__ void k_wprep(const float* __restrict__ c1w, float* __restrict__ out_loss) {
    int idx = blockIdx.x * 256 + threadIdx.x;   // 0..36863
    if (idx == 0) out_loss[0] = 0.f;
    int slot = idx & 15;
    int co = (idx >> 4) & 63;
    int rest = idx >> 10;                        // chunk*9 + tap
    int tap = rest % 9, chunk = rest / 9;
    int p = slot >> 2, pos = slot & 3;
    int cin = 2 * p + (pos & 1) + ((pos >> 1) << 3);
    float wv = c1w[(size_t)(co * 64 + chunk * 16 + cin) * 9 + tap];
    g_wpack[idx] = __float2half_rn(wv);
}

// ---------------- 1: per-(b,c) sums of sr / tg / tg^2 (float4) ----------------
__global__ void k_colsum(const float* __restrict__ sr, const float* __restrict__ tg) {
    int bc = blockIdx.x;
    const float4* ps = (const float4*)(sr + (size_t)bc * HWC);
    const float4* pt = (const float4*)(tg + (size_t)bc * HWC);
    float s0 = 0.f, s1 = 0.f, s2 = 0.f;
    for (int i = threadIdx.x; i < 2304; i += 256) {
        float4 a = ps[i], b = pt[i];
        s0 += a.x + a.y + a.z + a.w;
        s1 += b.x + b.y + b.z + b.w;
        s2 += b.x * b.x + b.y * b.y + b.z * b.z + b.w * b.w;
    }
    __shared__ float red[256];
    s0 = bsum256(s0, red); s1 = bsum256(s1, red); s2 = bsum256(s2, red);
    if (threadIdx.x == 0) { g_tsum[bc] = s0; g_T1[bc] = s1; g_T2[bc] = s2; }
}

// ---------------- 2: op = W*src + bias; opn; u = W^T opn; zero v ----------------
__global__ void k_opu(const float* __restrict__ ww, const float* __restrict__ wb, int first) {
    int bn = blockIdx.x; int b = bn >> 4, n = bn & 15; int c = threadIdx.x;
    __shared__ float src[64], opn[64], red[64];
    src[c] = first ? g_tsum[b * 64 + c] : g_v[bn * 64 + c];
    __syncthreads();
    const float* wr = ww + (size_t)(n * 64 + c) * 64;
    float a = 0.f;
#pragma unroll 8
    for (int cp = 0; cp < 64; cp++) a = fmaf(wr[cp], src[cp], a);
    float op = a + (first ? wb[n * 64 + c] * 9216.f : wb[n * 64 + c]);
    g_op[bn * 64 + c] = op;
    red[c] = op * op; __syncthreads();
#pragma unroll
    for (int s = 32; s > 0; s >>= 1) { if (c < s) red[c] += red[c + s]; __syncthreads(); }
    float nrm = fmaxf(sqrtf(red[0]), 1e-12f);
    opn[c] = op / nrm;
    __syncthreads();
    float u = 0.f;
    for (int cp = 0; cp < 64; cp++) u = fmaf(ww[(size_t)(n * 64 + cp) * 64 + c], opn[cp], u);
    g_u[bn * 64 + c] = u;
    g_v[bn * 64 + c] = 0.f;
}

// ---------------- 2b: final op + analytic GN1 affine; zero GN2 acc ----------------
__global__ void k_opfin(const float* __restrict__ ww, const float* __restrict__ wb,
                        const float* __restrict__ g1g, const float* __restrict__ g1b) {
    int bn = blockIdx.x; int b = bn >> 4, n = bn & 15; int c = threadIdx.x;
    __shared__ float vs[64];
    vs[c] = g_v[bn * 64 + c];
    __syncthreads();
    const float* wr = ww + (size_t)(n * 64 + c) * 64;
    float a = 0.f;
#pragma unroll 8
    for (int cp = 0; cp < 64; cp++) a = fmaf(wr[cp], vs[cp], a);
    float op = a + wb[n * 64 + c];
    g_op[bn * 64 + c] = op;
    float t1 = g_T1[b * 64 + c], t2 = g_T2[b * 64 + c];
    float s1 = t1 + 9216.f * op;
    float s2 = t2 + 2.f * op * t1 + 9216.f * op * op;
    s1 += __shfl_xor_sync(0xffffffffu, s1, 1); s1 += __shfl_xor_sync(0xffffffffu, s1, 2);
    s2 += __shfl_xor_sync(0xffffffffu, s2, 1); s2 += __shfl_xor_sync(0xffffffffu, s2, 2);
    float mu  = s1 * (1.f / 36864.f);
    float var = s2 * (1.f / 36864.f) - mu * mu;
    float inv = rsqrtf(var + EPSN);
    g_A1[bn * 64 + c] = g1g[c] * inv;
    g_D1[bn * 64 + c] = (op - mu) * inv * g1g[c] + g1b[c];
    g_gn2s[bn * 64 + c] = 0.f; g_gn2q[bn * 64 + c] = 0.f;
}

// ---------------- 3: logits + per-block online softmax partials ----------------
__global__ void k_logits(const float* __restrict__ sr) {
    int b = blockIdx.y, blk = blockIdx.x;
    int hw = blk * 256 + threadIdx.x;
    int tid = threadIdx.x;
    __shared__ float us[1024];
    __shared__ float tr[16 * 257];
    for (int i = tid; i < 1024; i += 256) us[i] = g_u[b * 1024 + i];
    __syncthreads();
    float acc[16];
#pragma unroll
    for (int n = 0; n < 16; n++) acc[n] = 0.f;
    const float* sp = sr + (size_t)b * 64 * HWC + hw;
    for (int c = 0; c < 64; c++) {
        float v = sp[(size_t)c * HWC];
#pragma unroll
        for (int n = 0; n < 16; n++) acc[n] = fmaf(us[n * 64 + c], v, acc[n]);
    }
#pragma unroll
    for (int n = 0; n < 16; n++) {
        g_logits[(size_t)(b * 16 + n) * HWC + hw] = acc[n];
        tr[n * 257 + tid] = acc[n];
    }
    __syncthreads();
    int w = tid >> 5, lane = tid & 31;
#pragma unroll
    for (int nn = 0; nn < 2; nn++) {
        int n = w * 2 + nn;
        float v[8]; float mx = -1e30f;
#pragma unroll
        for (int j = 0; j < 8; j++) { v[j] = tr[n * 257 + lane + 32 * j]; mx = fmaxf(mx, v[j]); }
#pragma unroll
        for (int o = 16; o > 0; o >>= 1) mx = fmaxf(mx, __shfl_xor_sync(0xffffffffu, mx, o));
        float s = 0.f;
#pragma unroll
        for (int j = 0; j < 8; j++) s += expf(v[j] - mx);
        s = wred(s);
        if (lane == 0) g_pms[(b * 16 + n) * 36 + blk] = make_float2(mx, s);
    }
}

// ---------------- 3b: combine 36 partials per bn ----------------
__global__ void k_red() {
    int bn = threadIdx.x;   // 128
    float M = -1e30f;
    for (int i = 0; i < 36; i++) M = fmaxf(M, g_pms[bn * 36 + i].x);
    float S = 0.f;
    for (int i = 0; i < 36; i++) {
        float2 p = g_pms[bn * 36 + i];
        S += p.y * expf(p.x - M);
    }
    g_Ms[bn] = make_float2(M, 1.f / S);
}

// ---------------- 3c: v[b,n,c] = sum_hw sr*softmax(logits); cof inline ----------------
__global__ void k_v(const float* __restrict__ sr, float* __restrict__ extra) {
    int ch = blockIdx.x;   // 16 chunks of 576 pixels
    int b  = blockIdx.y;
    int hw0 = ch * 576;
    int tid = threadIdx.x;
    __shared__ float cof_s[16 * 576];
    __shared__ float2 Ms[16];
    if (tid < 16) Ms[tid] = g_Ms[b * 16 + tid];
    __syncthreads();
    for (int idx = tid; idx < 9216; idx += 256) {
        int n = idx / 576, k = idx - n * 576;
        float l = g_logits[(size_t)(b * 16 + n) * HWC + hw0 + k];
        float c = expf(l - Ms[n].x) * Ms[n].y;
        cof_s[n * 576 + k] = c;
        if (extra) extra[(size_t)(b * 16 + n) * HWC + hw0 + k] = c;
    }
    __syncthreads();
    int w = tid >> 5, lane = tid & 31;
    for (int c = w; c < 64; c += 8) {
        const float* sp = sr + (size_t)(b * 64 + c) * HWC + hw0;
        float a[16];
#pragma unroll
        for (int n = 0; n < 16; n++) a[n] = 0.f;
        for (int k = lane; k < 576; k += 32) {
            float s = sp[k];
#pragma unroll
            for (int n = 0; n < 16; n++) a[n] = fmaf(s, cof_s[n * 576 + k], a[n]);
        }
#pragma unroll
        for (int n = 0; n < 16; n++) {
            float r = wred(a[n]);
            if (lane == 0) atomicAdd(&g_v[(b * 16 + n) * 64 + c], r);
        }
    }
}

// ---------------- 4: materialize GN1+ReLU input as fp16 channel-last ----------------
// g_x[((bn*4+chunk)*HWC + px)*16 + slot]; slot pair (2j,2j+1): j even {j,j+1}, j odd {j+7,j+8}
__global__ void __launch_bounds__(256) k_iprep(const float* __restrict__ tg) {
    int b = blockIdx.y;
    int px = blockIdx.x * 256 + threadIdx.x;
    __shared__ float As[1024], Ds[1024];
    for (int i = threadIdx.x; i < 1024; i += 256) {
        As[i] = g_A1[b * 1024 + i]; Ds[i] = g_D1[b * 1024 + i];
    }
    __syncthreads();
    float t[64];
    const float* tp = tg + (size_t)b * 64 * HWC + px;
#pragma unroll
    for (int c = 0; c < 64; c++) t[c] = tp[(size_t)c * HWC];
    for (int n = 0; n < 16; n++) {
        const float* A = As + n * 64; const float* D = Ds + n * 64;
        int bn = b * 16 + n;
#pragma unroll
        for (int chunk = 0; chunk < 4; chunk++) {
            __half2 hbuf[8];
#pragma unroll
            for (int j = 0; j < 8; j++) {
                int cin0 = (j & 1) ? (j + 7) : j;
                int c0 = chunk * 16 + cin0, c1 = c0 + 1;
                float v0 = fmaxf(fmaf(t[c0], A[c0], D[c0]), 0.f);
                float v1 = fmaxf(fmaf(t[c1], A[c1], D[c1]), 0.f);
                hbuf[j] = __floats2half2_rn(v0, v1);
            }
            uint4* dst = (uint4*)(g_x + ((size_t)(bn * 4 + chunk) * HWC + px) * 16);
            dst[0] = ((uint4*)hbuf)[0];
            dst[1] = ((uint4*)hbuf)[1];
        }
    }
}

// ---------------- 5: conv3x3(64->64) mma fp16; fills are pure vector copies --------
__global__ void __launch_bounds__(256, 2) k_conv1(const float* __restrict__ c1b) {
    int bn = blockIdx.z;
    int gx0 = blockIdx.x * 16, gy0 = blockIdx.y * 16;
    int tid = threadIdx.x;
    int warp = tid >> 5, lane = tid & 31;
    int gid = lane >> 2, tg4 = lane & 3;
    int mgroup = warp & 1, ngroup = warp >> 1;

    __shared__ __half in_s[324 * 16];
    __shared__ __half w_s[9 * 64 * 16];
    __shared__ float Bs[64];

    if (tid < 64) Bs[tid] = c1b[tid];

    float acc[2][8][4];
#pragma unroll
    for (int s = 0; s < 2; s++)
#pragma unroll
        for (int t = 0; t < 8; t++) { acc[s][t][0] = 0.f; acc[s][t][1] = 0.f; acc[s][t][2] = 0.f; acc[s][t][3] = 0.f; }

    int sidx[8];
#pragma unroll
    for (int t = 0; t < 8; t++) {
        int n = ngroup * 64 + t * 8 + gid;
        sidx[t] = (n >> 4) * 18 + (n & 15);
    }

    const uint4* wp4 = (const uint4*)g_wpack;
    const uint4* xsrc = (const uint4*)g_x;

    for (int cc4 = 0; cc4 < 4; cc4++) {
        __syncthreads();
        // weights: 1152 uint4 copy
        {
            uint4* ws4 = (uint4*)w_s;
            const uint4* src = wp4 + cc4 * 1152;
#pragma unroll
            for (int i = 0; i < 4; i++) ws4[tid + i * 256] = src[tid + i * 256];
            int idx = tid + 1024;
            if (idx < 1152) ws4[idx] = src[idx];
        }
        // input: 648 predicated uint4 copies from g_x
        size_t plane = (size_t)(bn * 4 + cc4) * HWC;
        for (int idx = tid; idx < 648; idx += 256) {
            int r = idx / 36;
            int q = idx - r * 36;
            int pxr = q >> 1, hs = q & 1;
            int gy = gy0 + r - 1, gx = gx0 + pxr - 1;
            uint4 v = make_uint4(0u, 0u, 0u, 0u);
            if ((unsigned)gy < 96u && (unsigned)gx < 96u)
                v = xsrc[(plane + gy * 96 + gx) * 2 + hs];
            ((uint4*)in_s)[(r * 18 + pxr) * 2 + hs] = v;
        }
        __syncthreads();
#pragma unroll
        for (int ks = 0; ks < 9; ks++) {
            int toff = (ks / 3) * 18 + (ks % 3);
            uint2 afr[2][2];
#pragma unroll
            for (int s = 0; s < 2; s++) {
                int co_r0 = mgroup * 32 + s * 16 + gid;
                afr[s][0] = *(const uint2*)(w_s + (ks * 64 + co_r0) * 16 + tg4 * 4);
                afr[s][1] = *(const uint2*)(w_s + (ks * 64 + co_r0 + 8) * 16 + tg4 * 4);
            }
#pragma unroll
            for (int t = 0; t < 8; t++) {
                uint2 bb = *(const uint2*)(in_s + (toff + sidx[t]) * 16 + tg4 * 4);
#pragma unroll
                for (int s = 0; s < 2; s++) {
                    asm volatile("mma.sync.aligned.m16n8k16.row.col.f32.f16.f16.f32 "
                                 "{%0,%1,%2,%3}, {%4,%5,%6,%7}, {%8,%9}, {%0,%1,%2,%3};"
                                 : "+f"(acc[s][t][0]), "+f"(acc[s][t][1]),
                                   "+f"(acc[s][t][2]), "+f"(acc[s][t][3])
                                 : "r"(afr[s][0].x), "r"(afr[s][1].x),
                                   "r"(afr[s][0].y), "r"(afr[s][1].y),
                                   "r"(bb.x), "r"(bb.y));
                }
            }
        }
    }

    // epilogue: bias, store y1, GN2 stats
#pragma unroll
    for (int s = 0; s < 2; s++) {
        int co0 = mgroup * 32 + s * 16 + gid;
        int co1 = co0 + 8;
        float b0v = Bs[co0], b1v = Bs[co1];
        float s0 = 0.f, q0 = 0.f, s1 = 0.f, q1 = 0.f;
        float* yb0 = g_y1 + (size_t)(bn * 64 + co0) * HWC;
        float* yb1 = g_y1 + (size_t)(bn * 64 + co1) * HWC;
#pragma unroll
        for (int t = 0; t < 8; t++) {
            int n = ngroup * 64 + t * 8 + tg4 * 2;
            int r = n >> 4, c = n & 15;
            size_t po = (size_t)(gy0 + r) * 96 + gx0 + c;
            float v00 = acc[s][t][0] + b0v, v01 = acc[s][t][1] + b0v;
            float v10 = acc[s][t][2] + b1v, v11 = acc[s][t][3] + b1v;
            yb0[po] = v00; yb0[po + 1] = v01;
            yb1[po] = v10; yb1[po + 1] = v11;
            s0 += v00 + v01; q0 += v00 * v00 + v01 * v01;
            s1 += v10 + v11; q1 += v10 * v10 + v11 * v11;
        }
        s0 += __shfl_xor_sync(0xffffffffu, s0, 1); s0 += __shfl_xor_sync(0xffffffffu, s0, 2);
        q0 += __shfl_xor_sync(0xffffffffu, q0, 1); q0 += __shfl_xor_sync(0xffffffffu, q0, 2);
        s1 += __shfl_xor_sync(0xffffffffu, s1, 1); s1 += __shfl_xor_sync(0xffffffffu, s1, 2);
        q1 += __shfl_xor_sync(0xffffffffu, q1, 1); q1 += __shfl_xor_sync(0xffffffffu, q1, 2);
        if (tg4 == 0) {
            atomicAdd(&g_gn2s[bn * 64 + co0], s0); atomicAdd(&g_gn2q[bn * 64 + co0], q0);
            atomicAdd(&g_gn2s[bn * 64 + co1], s1); atomicAdd(&g_gn2q[bn * 64 + co1], q1);
        }
    }
}

// ---------------- 6: GN2 affine params ----------------
__global__ void k_gn2fin(const float* __restrict__ g2g, const float* __restrict__ g2b) {
    int bn = blockIdx.x, c = threadIdx.x;
    float s = g_gn2s[bn * 64 + c], q = g_gn2q[bn * 64 + c];
    s += __shfl_xor_sync(0xffffffffu, s, 1); s += __shfl_xor_sync(0xffffffffu, s, 2);
    q += __shfl_xor_sync(0xffffffffu, q, 1); q += __shfl_xor_sync(0xffffffffu, q, 2);
    float mu = s * (1.f / 36864.f), var = q * (1.f / 36864.f) - mu * mu;
    float inv = rsqrtf(var + EPSN);
    g_A1[bn * 64 + c] = g2g[c] * inv;
    g_D1[bn * 64 + c] = g2b[c] - mu * inv * g2g[c];
}

// ---------------- 7: fused GN2+ReLU+conv3x3(64->1) -> msk ----------------
__global__ void __launch_bounds__(256) k_conv2(const float* __restrict__ c2w,
                                               const float* __restrict__ c2b,
                                               float* __restrict__ msk) {
    int bn = blockIdx.z; int gy0 = blockIdx.y * 16, gx0 = blockIdx.x * 16;
    int t = threadIdx.x, ty = t >> 4, tx = t & 15;
    __shared__ float tile[8 * 324];
    __shared__ float w2[576];
    __shared__ float A[64], D[64];
    for (int i = t; i < 576; i += 256) w2[i] = c2w[i];
    if (t < 64) { A[t] = g_A1[bn * 64 + t]; D[t] = g_D1[bn * 64 + t]; }
    float acc = c2b[0];
    const float* y = g_y1 + (size_t)bn * 64 * HWC;
    for (int cc = 0; cc < 64; cc += 8) {
        __syncthreads();
        for (int idx = t; idx < 2592; idx += 256) {
            int ch = idx / 324, rem = idx - ch * 324, r = rem / 18, c = rem - r * 18;
            int gy = gy0 + r - 1, gx = gx0 + c - 1;
            float v = 0.f;
            if ((unsigned)gy < 96u && (unsigned)gx < 96u)
                v = fmaxf(fmaf(y[(size_t)(cc + ch) * HWC + gy * 96 + gx], A[cc + ch], D[cc + ch]), 0.f);
            tile[idx] = v;
        }
        __syncthreads();
#pragma unroll
        for (int ch = 0; ch < 8; ch++)
#pragma unroll
            for (int kr = 0; kr < 3; kr++)
#pragma unroll
                for (int kc = 0; kc < 3; kc++)
                    acc = fmaf(w2[(cc + ch) * 9 + kr * 3 + kc],
                               tile[ch * 324 + (ty + kr) * 18 + tx + kc], acc);
    }
    msk[(size_t)bn * HWC + (gy0 + ty) * 96 + gx0 + tx] = acc;
}

// ---------------- 8: softmax of msk + center loss + IN1 stats (single pass) ------
__global__ void k_msk_stats(const float* __restrict__ msk, float* __restrict__ out_loss) {
    int bn = blockIdx.x; int t = threadIdx.x;
    const float* m = msk + (size_t)bn * HWC;
    __shared__ float red[256];
    float mx = -1e30f;
    for (int i = t; i < HWC; i += 256) mx = fmaxf(mx, m[i]);
    mx = bmax256(mx, red);
    float se = 0.f, s1 = 0.f, s2 = 0.f;
    float ey = 0.f, ex = 0.f, ey2 = 0.f, ex2 = 0.f;
    const float st = 2.f / 95.f;
    for (int i = t; i < HWC; i += 256) {
        float v = m[i];
        float e = expf(v - mx);
        se += e; s1 += v; s2 += v * v;
        int ii = i / 96, jj = i - ii * 96;
        float yv = -1.f + st * ii, xv = -1.f + st * jj;
        ey += e * yv; ex += e * xv; ey2 += e * yv * yv; ex2 += e * xv * xv;
    }
    se = bsum256(se, red); s1 = bsum256(s1, red); s2 = bsum256(s2, red);
    ey = bsum256(ey, red); ex = bsum256(ex, red);
    ey2 = bsum256(ey2, red); ex2 = bsum256(ex2, red);
    if (t == 0) {
        float inv_se = 1.f / se;
        ey *= inv_se; ex *= inv_se; ey2 *= inv_se; ex2 *= inv_se;
        float lp = ey2 - ey * ey + ex2 - ex * ex;
        atomicAdd(out_loss, lp * (1.f / 128.f));
        float mu = s1 / 9216.f; float var = s2 / 9216.f - mu * mu;
        g_mstat[2 * bn] = mu; g_mstat[2 * bn + 1] = rsqrtf(var + EPSN);
        g_in2s[bn] = 0.f; g_in2q[bn] = 0.f;
    }
}

// ---------------- 10: IN1+ReLU+1x1(16->16) + IN2 stats ----------------
__global__ void k_gen1(const float* __restrict__ msk, const float* __restrict__ in1g,
                       const float* __restrict__ in1b, const float* __restrict__ c3w,
                       const float* __restrict__ c3b) {
    int b = blockIdx.y; int hw = blockIdx.x * 256 + threadIdx.x;
    int t = threadIdx.x;
    __shared__ float w3[256], b3[16], mus[16], invs[16], g1[16], bb1[16];
    __shared__ float bs_[16], bq_[16];
    if (t < 256) w3[t] = c3w[t];
    if (t < 16) {
        b3[t] = c3b[t]; int bn = b * 16 + t;
        mus[t] = g_mstat[2 * bn]; invs[t] = g_mstat[2 * bn + 1];
        g1[t] = in1g[t]; bb1[t] = in1b[t]; bs_[t] = 0.f; bq_[t] = 0.f;
    }
    __syncthreads();
    float r[16];
#pragma unroll
    for (int n = 0; n < 16; n++) {
        float m = msk[(size_t)(b * 16 + n) * HWC + hw];
        r[n] = fmaxf((m - mus[n]) * invs[n] * g1[n] + bb1[n], 0.f);
    }
#pragma unroll
    for (int o = 0; o < 16; o++) {
        float a = b3[o];
#pragma unroll
        for (int n = 0; n < 16; n++) a = fmaf(w3[o * 16 + n], r[n], a);
        g_g2[(size_t)(b * 16 + o) * HWC + hw] = a;
        float s = wred(a), q = wred(a * a);
        if ((t & 31) == 0) { atomicAdd(&bs_[o], s); atomicAdd(&bq_[o], q); }
    }
    __syncthreads();
    if (t < 16) { atomicAdd(&g_in2s[b * 16 + t], bs_[t]); atomicAdd(&g_in2q[b * 16 + t], bq_[t]); }
}

// ---------------- 11: IN2 stats finalize ----------------
__global__ void k_in2fin() {
    int i = threadIdx.x;
    float mu = g_in2s[i] / 9216.f;
    float var = g_in2q[i] / 9216.f - mu * mu;
    g_in2stat[2 * i] = mu; g_in2stat[2 * i + 1] = rsqrtf(var + EPSN);
}

// ---------------- 12: IN2+ReLU+1x1(16->3)+sigmoid -> rec ----------------
__global__ void k_rec(const float* __restrict__ in2g, const float* __restrict__ in2b,
                      const float* __restrict__ c4w, const float* __restrict__ c4b,
                      float* __restrict__ out) {
    int b = blockIdx.y; int hw = blockIdx.x * 256 + threadIdx.x; int t = threadIdx.x;
    __shared__ float w4[48], mus[16], invs[16], g2[16], bb2[16];
    if (t < 48) w4[t] = c4w[t];
    if (t < 16) {
        int bo = b * 16 + t;
        mus[t] = g_in2stat[2 * bo]; invs[t] = g_in2stat[2 * bo + 1];
        g2[t] = in2g[t]; bb2[t] = in2b[t];
    }
    __syncthreads();
    float x[16];
#pragma unroll
    for (int o = 0; o < 16; o++) {
        float v = g_g2[(size_t)(b * 16 + o) * HWC + hw];
        x[o] = fmaxf((v - mus[o]) * invs[o] * g2[o] + bb2[o], 0.f);
    }
#pragma unroll
    for (int o2 = 0; o2 < 3; o2++) {
        float a = c4b[o2];
#pragma unroll
        for (int o = 0; o < 16; o++) a = fmaf(w4[o2 * 16 + o], x[o], a);
        out[(size_t)(b * 3 + o2) * HWC + hw] = 1.f / (1.f + expf(-a));
    }
}

// ---------------- 13: op_out = op[bnc] * msk[bn,hw] (float4) ----------------
__global__ void k_opout(const float* __restrict__ msk, float* __restrict__ out) {
    int bn = blockIdx.y; int i4 = blockIdx.x * 256 + threadIdx.x;   // 0..2303
    __shared__ float ops[64];
    if (threadIdx.x < 64) ops[threadIdx.x] = g_op[bn * 64 + threadIdx.x];
    __syncthreads();
    float4 m4 = ((const float4*)(msk + (size_t)bn * HWC))[i4];
    float* ob = out + (size_t)bn * 64 * HWC;
#pragma unroll 8
    for (int c = 0; c < 64; c++) {
        float s = ops[c];
        float4 r; r.x = s * m4.x; r.y = s * m4.y; r.z = s * m4.z; r.w = s * m4.w;
        ((float4*)(ob + (size_t)c * HWC))[i4] = r;
    }
}

// ---------------- launch ----------------
extern "C" void kernel_launch(void* const* d_in, const int* in_sizes, int n_in,
                              void* d_out, int out_size) {
    const float* sr   = (const float*)d_in[0];
    const float* tg   = (const float*)d_in[1];
    const float* ww   = (const float*)d_in[2];
    const float* wb   = (const float*)d_in[3];
    const float* gn1g = (const float*)d_in[4];
    const float* gn1b = (const float*)d_in[5];
    const float* c1w  = (const float*)d_in[6];
    const float* c1b  = (const float*)d_in[7];
    const float* gn2g = (const float*)d_in[8];
    const float* gn2b = (const float*)d_in[9];
    const float* c2w  = (const float*)d_in[10];
    const float* c2b  = (const float*)d_in[11];
    const float* in1g = (const float*)d_in[12];
    const float* in1b = (const float*)d_in[13];
    const float* c3w  = (const float*)d_in[14];
    const float* c3b  = (const float*)d_in[15];
    const float* in2g = (const float*)d_in[16];
    const float* in2b = (const float*)d_in[17];
    const float* c4w  = (const float*)d_in[18];
    const float* c4b  = (const float*)d_in[19];
    float* out = (float*)d_out;
    float* out_msk  = out + 75497472;
    float* out_rec  = out + 76677120;
    float* out_loss = out + 76898304;
    float* out_cof  = out + 76898305;

    k_wprep<<<144, 256>>>(c1w, out_loss);
    k_colsum<<<512, 256>>>(sr, tg);
    k_opu<<<128, 64>>>(ww, wb, 1);
    for (int it = 0; it < 3; it++) {
        k_logits<<<dim3(36, 8), 256>>>(sr);
        k_red<<<1, 128>>>();
        k_v<<<dim3(16, 8), 256>>>(sr, it == 2 ? out_cof : (float*)nullptr);
        if (it < 2) k_opu<<<128, 64>>>(ww, wb, 0);
        else        k_opfin<<<128, 64>>>(ww, wb, gn1g, gn1b);
    }
    k_iprep<<<dim3(36, 8), 256>>>(tg);
    k_conv1<<<dim3(6, 6, 128), 256>>>(c1b);
    k_gn2fin<<<128, 64>>>(gn2g, gn2b);
    k_conv2<<<dim3(6, 6, 128), 256>>>(c2w, c2b, out_msk);
    k_msk_stats<<<128, 256>>>(out_msk, out_loss);
    k_gen1<<<dim3(36, 8), 256>>>(out_msk, in1g, in1b, c3w, c3b);
    k_in2fin<<<1, 128>>>();
    k_rec<<<dim3(36, 8), 256>>>(in2g, in2b, c4w, c4b, out_rec);
    k_opout<<<dim3(9, 128), 256>>>(out_msk, out);
}

// round 7
// speedup vs baseline: 1.5666x; 1.5666x over previous
#include <cuda_runtime.h>
#include <cuda_fp16.h>
#include <cstdint>
#include <cstddef>

#define HWC 9216
#define EPSN 1e-5f

// ---------------- scratch (__device__ globals; no allocation) ----------------
__device__ __align__(16) __half g_y1h[75497472]; // conv1 output fp16 [128,64,9216]
__device__ float g_logits[1179648];   // [128,9216]
__device__ float g_g2[1179648];       // gen-block intermediate [8,16,9216]
__device__ float g_tsum[512];         // sum_hw sr [8,64]
__device__ float g_T1[512];           // sum_hw tg
__device__ float g_T2[512];           // sum_hw tg^2
__device__ float g_op[8192];          // [128,64]
__device__ float g_u[8192];           // W^T opn
__device__ float g_v[8192];           // sum_hw sr*cof
__device__ float g_A1[8192];          // GN affine scale (GN1 then GN2)
__device__ float g_D1[8192];          // GN affine shift
__device__ float g_gn2s[8192];
__device__ float g_gn2q[8192];
__device__ float g_mstat[256];        // per-bn (mu, invstd) of msk
__device__ float g_in2s[128];
__device__ float g_in2q[128];
__device__ float g_in2stat[256];
__device__ float2 g_pms[4608];        // per-(bn,blk) online softmax partials (m,s)
__device__ float2 g_Ms[128];          // per-bn (M, 1/S)
__device__ __align__(16) __half g_wpack[36864];     // packed fp16 conv1 weights

// ---------------- helpers ----------------
__device__ __forceinline__ float wred(float v) {
#pragma unroll
    for (int o = 16; o > 0; o >>= 1) v += __shfl_xor_sync(0xffffffffu, v, o);
    return v;
}
__device__ __forceinline__ float bsum256(float v, float* red) {
    int t = threadIdx.x; red[t] = v; __syncthreads();
#pragma unroll
    for (int s = 128; s > 0; s >>= 1) { if (t < s) red[t] += red[t + s]; __syncthreads(); }
    float r = red[0]; __syncthreads(); return r;
}
__device__ __forceinline__ float bmax256(float v, float* red) {
    int t = threadIdx.x; red[t] = v; __syncthreads();
#pragma unroll
    for (int s = 128; s > 0; s >>= 1) { if (t < s) red[t] = fmaxf(red[t], red[t + s]); __syncthreads(); }
    float r = red[0]; __syncthreads(); return r;
}

// ---------------- 0: pack conv1 weights; zero loss accumulator ----------------
__global__ void k_wprep(const float* __restrict__ c1w, float* __restrict__ out_loss) {
    int idx = blockIdx.x * 256 + threadIdx.x;   // 0..36863
    if (idx == 0) out_loss[0] = 0.f;
    int slot = idx & 15;
    int co = (idx >> 4) & 63;
    int rest = idx >> 10;                        // chunk*9 + tap
    int tap = rest % 9, chunk = rest / 9;
    int p = slot >> 2, pos = slot & 3;
    int cin = 2 * p + (pos & 1) + ((pos >> 1) << 3);
    float wv = c1w[(size_t)(co * 64 + chunk * 16 + cin) * 9 + tap];
    g_wpack[idx] = __float2half_rn(wv);
}

// ---------------- 1: per-(b,c) sums of sr / tg / tg^2 (float4) ----------------
__global__ void k_colsum(const float* __restrict__ sr, const float* __restrict__ tg) {
    int bc = blockIdx.x;
    const float4* ps = (const float4*)(sr + (size_t)bc * HWC);
    const float4* pt = (const float4*)(tg + (size_t)bc * HWC);
    float s0 = 0.f, s1 = 0.f, s2 = 0.f;
    for (int i = threadIdx.x; i < 2304; i += 256) {
        float4 a = ps[i], b = pt[i];
        s0 += a.x + a.y + a.z + a.w;
        s1 += b.x + b.y + b.z + b.w;
        s2 += b.x * b.x + b.y * b.y + b.z * b.z + b.w * b.w;
    }
    __shared__ float red[256];
    s0 = bsum256(s0, red); s1 = bsum256(s1, red); s2 = bsum256(s2, red);
    if (threadIdx.x == 0) { g_tsum[bc] = s0; g_T1[bc] = s1; g_T2[bc] = s2; }
}

// ---------------- 2: op = W*src + bias; opn; u = W^T opn; zero v ----------------
__global__ void k_opu(const float* __restrict__ ww, const float* __restrict__ wb, int first) {
    int bn = blockIdx.x; int b = bn >> 4, n = bn & 15; int c = threadIdx.x;
    __shared__ float src[64], opn[64], red[64];
    src[c] = first ? g_tsum[b * 64 + c] : g_v[bn * 64 + c];
    __syncthreads();
    const float* wr = ww + (size_t)(n * 64 + c) * 64;
    float a = 0.f;
#pragma unroll 8
    for (int cp = 0; cp < 64; cp++) a = fmaf(wr[cp], src[cp], a);
    float op = a + (first ? wb[n * 64 + c] * 9216.f : wb[n * 64 + c]);
    g_op[bn * 64 + c] = op;
    red[c] = op * op; __syncthreads();
#pragma unroll
    for (int s = 32; s > 0; s >>= 1) { if (c < s) red[c] += red[c + s]; __syncthreads(); }
    float nrm = fmaxf(sqrtf(red[0]), 1e-12f);
    opn[c] = op / nrm;
    __syncthreads();
    float u = 0.f;
    for (int cp = 0; cp < 64; cp++) u = fmaf(ww[(size_t)(n * 64 + cp) * 64 + c], opn[cp], u);
    g_u[bn * 64 + c] = u;
    g_v[bn * 64 + c] = 0.f;
}

// ---------------- 2b: final op + analytic GN1 affine; zero GN2 acc ----------------
__global__ void k_opfin(const float* __restrict__ ww, const float* __restrict__ wb,
                        const float* __restrict__ g1g, const float* __restrict__ g1b) {
    int bn = blockIdx.x; int b = bn >> 4, n = bn & 15; int c = threadIdx.x;
    __shared__ float vs[64];
    vs[c] = g_v[bn * 64 + c];
    __syncthreads();
    const float* wr = ww + (size_t)(n * 64 + c) * 64;
    float a = 0.f;
#pragma unroll 8
    for (int cp = 0; cp < 64; cp++) a = fmaf(wr[cp], vs[cp], a);
    float op = a + wb[n * 64 + c];
    g_op[bn * 64 + c] = op;
    float t1 = g_T1[b * 64 + c], t2 = g_T2[b * 64 + c];
    float s1 = t1 + 9216.f * op;
    float s2 = t2 + 2.f * op * t1 + 9216.f * op * op;
    s1 += __shfl_xor_sync(0xffffffffu, s1, 1); s1 += __shfl_xor_sync(0xffffffffu, s1, 2);
    s2 += __shfl_xor_sync(0xffffffffu, s2, 1); s2 += __shfl_xor_sync(0xffffffffu, s2, 2);
    float mu  = s1 * (1.f / 36864.f);
    float var = s2 * (1.f / 36864.f) - mu * mu;
    float inv = rsqrtf(var + EPSN);
    g_A1[bn * 64 + c] = g1g[c] * inv;
    g_D1[bn * 64 + c] = (op - mu) * inv * g1g[c] + g1b[c];
    g_gn2s[bn * 64 + c] = 0.f; g_gn2q[bn * 64 + c] = 0.f;
}

// ---------------- 3: logits + per-block online softmax partials ----------------
__global__ void k_logits(const float* __restrict__ sr) {
    int b = blockIdx.y, blk = blockIdx.x;
    int hw = blk * 256 + threadIdx.x;
    int tid = threadIdx.x;
    __shared__ float us[1024];
    __shared__ float tr[16 * 257];
    for (int i = tid; i < 1024; i += 256) us[i] = g_u[b * 1024 + i];
    __syncthreads();
    float acc[16];
#pragma unroll
    for (int n = 0; n < 16; n++) acc[n] = 0.f;
    const float* sp = sr + (size_t)b * 64 * HWC + hw;
    for (int c = 0; c < 64; c++) {
        float v = sp[(size_t)c * HWC];
#pragma unroll
        for (int n = 0; n < 16; n++) acc[n] = fmaf(us[n * 64 + c], v, acc[n]);
    }
#pragma unroll
    for (int n = 0; n < 16; n++) {
        g_logits[(size_t)(b * 16 + n) * HWC + hw] = acc[n];
        tr[n * 257 + tid] = acc[n];
    }
    __syncthreads();
    int w = tid >> 5, lane = tid & 31;
#pragma unroll
    for (int nn = 0; nn < 2; nn++) {
        int n = w * 2 + nn;
        float v[8]; float mx = -1e30f;
#pragma unroll
        for (int j = 0; j < 8; j++) { v[j] = tr[n * 257 + lane + 32 * j]; mx = fmaxf(mx, v[j]); }
#pragma unroll
        for (int o = 16; o > 0; o >>= 1) mx = fmaxf(mx, __shfl_xor_sync(0xffffffffu, mx, o));
        float s = 0.f;
#pragma unroll
        for (int j = 0; j < 8; j++) s += expf(v[j] - mx);
        s = wred(s);
        if (lane == 0) g_pms[(b * 16 + n) * 36 + blk] = make_float2(mx, s);
    }
}

// ---------------- 3b: combine 36 partials per bn ----------------
__global__ void k_red() {
    int bn = threadIdx.x;   // 128
    float M = -1e30f;
    for (int i = 0; i < 36; i++) M = fmaxf(M, g_pms[bn * 36 + i].x);
    float S = 0.f;
    for (int i = 0; i < 36; i++) {
        float2 p = g_pms[bn * 36 + i];
        S += p.y * expf(p.x - M);
    }
    g_Ms[bn] = make_float2(M, 1.f / S);
}

// ---------------- 3c: v[b,n,c] = sum_hw sr*softmax(logits); cof inline ----------------
__global__ void k_v(const float* __restrict__ sr, float* __restrict__ extra) {
    int ch = blockIdx.x;   // 16 chunks of 576 pixels
    int b  = blockIdx.y;
    int hw0 = ch * 576;
    int tid = threadIdx.x;
    __shared__ float cof_s[16 * 576];
    __shared__ float2 Ms[16];
    if (tid < 16) Ms[tid] = g_Ms[b * 16 + tid];
    __syncthreads();
    for (int idx = tid; idx < 9216; idx += 256) {
        int n = idx / 576, k = idx - n * 576;
        float l = g_logits[(size_t)(b * 16 + n) * HWC + hw0 + k];
        float c = expf(l - Ms[n].x) * Ms[n].y;
        cof_s[n * 576 + k] = c;
        if (extra) extra[(size_t)(b * 16 + n) * HWC + hw0 + k] = c;
    }
    __syncthreads();
    int w = tid >> 5, lane = tid & 31;
    for (int c = w; c < 64; c += 8) {
        const float* sp = sr + (size_t)(b * 64 + c) * HWC + hw0;
        float a[16];
#pragma unroll
        for (int n = 0; n < 16; n++) a[n] = 0.f;
        for (int k = lane; k < 576; k += 32) {
            float s = sp[k];
#pragma unroll
            for (int n = 0; n < 16; n++) a[n] = fmaf(s, cof_s[n * 576 + k], a[n]);
        }
#pragma unroll
        for (int n = 0; n < 16; n++) {
            float r = wred(a[n]);
            if (lane == 0) atomicAdd(&g_v[(b * 16 + n) * 64 + c], r);
        }
    }
}

// ---------------- 5: fused GN1+ReLU+conv3x3(64->64) via mma fp16 ----------------
// R5-style fills: weights uint4 from g_wpack, input GN+ReLU from L2-resident tg
// with shift-only indexing + conflict-free half2 stores. y1 stored as fp16.
__global__ void __launch_bounds__(256, 2) k_conv1(const float* __restrict__ tg,
                                                  const float* __restrict__ c1b) {
    int bn = blockIdx.z, b = bn >> 4;
    int gx0 = blockIdx.x * 16, gy0 = blockIdx.y * 16;
    int tid = threadIdx.x;
    int warp = tid >> 5, lane = tid & 31;
    int gid = lane >> 2, tg4 = lane & 3;
    int mgroup = warp & 1, ngroup = warp >> 1;

    __shared__ __half in_s[324 * 16];
    __shared__ __half w_s[9 * 64 * 16];
    __shared__ float As[64], Ds[64], Bs[64];

    if (tid < 64) { As[tid] = g_A1[bn * 64 + tid]; Ds[tid] = g_D1[bn * 64 + tid]; Bs[tid] = c1b[tid]; }

    float acc[2][8][4];
#pragma unroll
    for (int s = 0; s < 2; s++)
#pragma unroll
        for (int t = 0; t < 8; t++) { acc[s][t][0] = 0.f; acc[s][t][1] = 0.f; acc[s][t][2] = 0.f; acc[s][t][3] = 0.f; }

    int sidx[8];
#pragma unroll
    for (int t = 0; t < 8; t++) {
        int n = ngroup * 64 + t * 8 + gid;
        sidx[t] = (n >> 4) * 18 + (n & 15);
    }

    const float* tgb = tg + (size_t)b * 64 * HWC;
    const uint4* wp4 = (const uint4*)g_wpack;

    for (int cc4 = 0; cc4 < 4; cc4++) {
        int cc = cc4 * 16;
        __syncthreads();
        // weights: 1152 uint4 copy
        {
            uint4* ws4 = (uint4*)w_s;
            const uint4* src = wp4 + cc4 * 1152;
#pragma unroll
            for (int i = 0; i < 4; i++) ws4[tid + i * 256] = src[tid + i * 256];
            int idx = tid + 1024;
            if (idx < 1152) ws4[idx] = src[idx];
        }
        // input halo tile: GN1 affine + ReLU -> half2, shift-only indexing
        for (int idx = tid; idx < 2592; idx += 256) {
            int sp = idx >> 3, j = idx & 7;
            int cin0 = (j & 1) ? (j + 7) : j;
            int rr = sp / 18, c2 = sp - rr * 18;
            int gy = gy0 + rr - 1, gx = gx0 + c2 - 1;
            float v0 = 0.f, v1 = 0.f;
            if ((unsigned)gy < 96u && (unsigned)gx < 96u) {
                int ch0 = cc + cin0;
                size_t base = (size_t)gy * 96 + gx;
                float t0 = tgb[(size_t)ch0 * HWC + base];
                float t1 = tgb[(size_t)(ch0 + 1) * HWC + base];
                v0 = fmaxf(fmaf(t0, As[ch0], Ds[ch0]), 0.f);
                v1 = fmaxf(fmaf(t1, As[ch0 + 1], Ds[ch0 + 1]), 0.f);
            }
            ((__half2*)in_s)[sp * 8 + j] = __floats2half2_rn(v0, v1);
        }
        __syncthreads();
#pragma unroll
        for (int ks = 0; ks < 9; ks++) {
            int toff = (ks / 3) * 18 + (ks % 3);
            uint2 afr[2][2];
#pragma unroll
            for (int s = 0; s < 2; s++) {
                int co_r0 = mgroup * 32 + s * 16 + gid;
                afr[s][0] = *(const uint2*)(w_s + (ks * 64 + co_r0) * 16 + tg4 * 4);
                afr[s][1] = *(const uint2*)(w_s + (ks * 64 + co_r0 + 8) * 16 + tg4 * 4);
            }
#pragma unroll
            for (int t = 0; t < 8; t++) {
                uint2 bb = *(const uint2*)(in_s + (toff + sidx[t]) * 16 + tg4 * 4);
#pragma unroll
                for (int s = 0; s < 2; s++) {
                    asm volatile("mma.sync.aligned.m16n8k16.row.col.f32.f16.f16.f32 "
                                 "{%0,%1,%2,%3}, {%4,%5,%6,%7}, {%8,%9}, {%0,%1,%2,%3};"
                                 : "+f"(acc[s][t][0]), "+f"(acc[s][t][1]),
                                   "+f"(acc[s][t][2]), "+f"(acc[s][t][3])
                                 : "r"(afr[s][0].x), "r"(afr[s][1].x),
                                   "r"(afr[s][0].y), "r"(afr[s][1].y),
                                   "r"(bb.x), "r"(bb.y));
                }
            }
        }
    }

    // epilogue: bias, fp16 store of y1, GN2 stats from the ROUNDED values
#pragma unroll
    for (int s = 0; s < 2; s++) {
        int co0 = mgroup * 32 + s * 16 + gid;
        int co1 = co0 + 8;
        float b0v = Bs[co0], b1v = Bs[co1];
        float s0 = 0.f, q0 = 0.f, s1 = 0.f, q1 = 0.f;
        __half2* yb0 = (__half2*)(g_y1h + (size_t)(bn * 64 + co0) * HWC);
        __half2* yb1 = (__half2*)(g_y1h + (size_t)(bn * 64 + co1) * HWC);
#pragma unroll
        for (int t = 0; t < 8; t++) {
            int n = ngroup * 64 + t * 8 + tg4 * 2;
            int r = n >> 4, c = n & 15;
            int po = ((gy0 + r) * 96 + gx0 + c) >> 1;
            __half2 h0 = __floats2half2_rn(acc[s][t][0] + b0v, acc[s][t][1] + b0v);
            __half2 h1 = __floats2half2_rn(acc[s][t][2] + b1v, acc[s][t][3] + b1v);
            yb0[po] = h0; yb1[po] = h1;
            float v00 = __low2float(h0), v01 = __high2float(h0);
            float v10 = __low2float(h1), v11 = __high2float(h1);
            s0 += v00 + v01; q0 += v00 * v00 + v01 * v01;
            s1 += v10 + v11; q1 += v10 * v10 + v11 * v11;
        }
        s0 += __shfl_xor_sync(0xffffffffu, s0, 1); s0 += __shfl_xor_sync(0xffffffffu, s0, 2);
        q0 += __shfl_xor_sync(0xffffffffu, q0, 1); q0 += __shfl_xor_sync(0xffffffffu, q0, 2);
        s1 += __shfl_xor_sync(0xffffffffu, s1, 1); s1 += __shfl_xor_sync(0xffffffffu, s1, 2);
        q1 += __shfl_xor_sync(0xffffffffu, q1, 1); q1 += __shfl_xor_sync(0xffffffffu, q1, 2);
        if (tg4 == 0) {
            atomicAdd(&g_gn2s[bn * 64 + co0], s0); atomicAdd(&g_gn2q[bn * 64 + co0], q0);
            atomicAdd(&g_gn2s[bn * 64 + co1], s1); atomicAdd(&g_gn2q[bn * 64 + co1], q1);
        }
    }
}

// ---------------- 6: GN2 affine params ----------------
__global__ void k_gn2fin(const float* __restrict__ g2g, const float* __restrict__ g2b) {
    int bn = blockIdx.x, c = threadIdx.x;
    float s = g_gn2s[bn * 64 + c], q = g_gn2q[bn * 64 + c];
    s += __shfl_xor_sync(0xffffffffu, s, 1); s += __shfl_xor_sync(0xffffffffu, s, 2);
    q += __shfl_xor_sync(0xffffffffu, q, 1); q += __shfl_xor_sync(0xffffffffu, q, 2);
    float mu = s * (1.f / 36864.f), var = q * (1.f / 36864.f) - mu * mu;
    float inv = rsqrtf(var + EPSN);
    g_A1[bn * 64 + c] = g2g[c] * inv;
    g_D1[bn * 64 + c] = g2b[c] - mu * inv * g2g[c];
}

// ---------------- 7: fused GN2+ReLU+conv3x3(64->1) -> msk (fp16 y1 reads) -------
__global__ void __launch_bounds__(256) k_conv2(const float* __restrict__ c2w,
                                               const float* __restrict__ c2b,
                                               float* __restrict__ msk) {
    int bn = blockIdx.z; int gy0 = blockIdx.y * 16, gx0 = blockIdx.x * 16;
    int t = threadIdx.x, ty = t >> 4, tx = t & 15;
    __shared__ float tile[8 * 324];
    __shared__ float w2[576];
    __shared__ float A[64], D[64];
    for (int i = t; i < 576; i += 256) w2[i] = c2w[i];
    if (t < 64) { A[t] = g_A1[bn * 64 + t]; D[t] = g_D1[bn * 64 + t]; }
    float acc = c2b[0];
    const __half* y = g_y1h + (size_t)bn * 64 * HWC;
    for (int cc = 0; cc < 64; cc += 8) {
        __syncthreads();
        for (int idx = t; idx < 2592; idx += 256) {
            int ch = idx / 324, rem = idx - ch * 324, r = rem / 18, c = rem - r * 18;
            int gy = gy0 + r - 1, gx = gx0 + c - 1;
            float v = 0.f;
            if ((unsigned)gy < 96u && (unsigned)gx < 96u) {
                float yv = __half2float(y[(size_t)(cc + ch) * HWC + gy * 96 + gx]);
                v = fmaxf(fmaf(yv, A[cc + ch], D[cc + ch]), 0.f);
            }
            tile[idx] = v;
        }
        __syncthreads();
#pragma unroll
        for (int ch = 0; ch < 8; ch++)
#pragma unroll
            for (int kr = 0; kr < 3; kr++)
#pragma unroll
                for (int kc = 0; kc < 3; kc++)
                    acc = fmaf(w2[(cc + ch) * 9 + kr * 3 + kc],
                               tile[ch * 324 + (ty + kr) * 18 + tx + kc], acc);
    }
    msk[(size_t)bn * HWC + (gy0 + ty) * 96 + gx0 + tx] = acc;
}

// ---------------- 8: softmax of msk + center loss + IN1 stats (single pass) ------
__global__ void k_msk_stats(const float* __restrict__ msk, float* __restrict__ out_loss) {
    int bn = blockIdx.x; int t = threadIdx.x;
    const float* m = msk + (size_t)bn * HWC;
    __shared__ float red[256];
    float mx = -1e30f;
    for (int i = t; i < HWC; i += 256) mx = fmaxf(mx, m[i]);
    mx = bmax256(mx, red);
    float se = 0.f, s1 = 0.f, s2 = 0.f;
    float ey = 0.f, ex = 0.f, ey2 = 0.f, ex2 = 0.f;
    const float st = 2.f / 95.f;
    for (int i = t; i < HWC; i += 256) {
        float v = m[i];
        float e = expf(v - mx);
        se += e; s1 += v; s2 += v * v;
        int ii = i / 96, jj = i - ii * 96;
        float yv = -1.f + st * ii, xv = -1.f + st * jj;
        ey += e * yv; ex += e * xv; ey2 += e * yv * yv; ex2 += e * xv * xv;
    }
    se = bsum256(se, red); s1 = bsum256(s1, red); s2 = bsum256(s2, red);
    ey = bsum256(ey, red); ex = bsum256(ex, red);
    ey2 = bsum256(ey2, red); ex2 = bsum256(ex2, red);
    if (t == 0) {
        float inv_se = 1.f / se;
        ey *= inv_se; ex *= inv_se; ey2 *= inv_se; ex2 *= inv_se;
        float lp = ey2 - ey * ey + ex2 - ex * ex;
        atomicAdd(out_loss, lp * (1.f / 128.f));
        float mu = s1 / 9216.f; float var = s2 / 9216.f - mu * mu;
        g_mstat[2 * bn] = mu; g_mstat[2 * bn + 1] = rsqrtf(var + EPSN);
        g_in2s[bn] = 0.f; g_in2q[bn] = 0.f;
    }
}

// ---------------- 10: IN1+ReLU+1x1(16->16) + IN2 stats ----------------
__global__ void k_gen1(const float* __restrict__ msk, const float* __restrict__ in1g,
                       const float* __restrict__ in1b, const float* __restrict__ c3w,
                       const float* __restrict__ c3b) {
    int b = blockIdx.y; int hw = blockIdx.x * 256 + threadIdx.x;
    int t = threadIdx.x;
    __shared__ float w3[256], b3[16], mus[16], invs[16], g1[16], bb1[16];
    __shared__ float bs_[16], bq_[16];
    if (t < 256) w3[t] = c3w[t];
    if (t < 16) {
        b3[t] = c3b[t]; int bn = b * 16 + t;
        mus[t] = g_mstat[2 * bn]; invs[t] = g_mstat[2 * bn + 1];
        g1[t] = in1g[t]; bb1[t] = in1b[t]; bs_[t] = 0.f; bq_[t] = 0.f;
    }
    __syncthreads();
    float r[16];
#pragma unroll
    for (int n = 0; n < 16; n++) {
        float m = msk[(size_t)(b * 16 + n) * HWC + hw];
        r[n] = fmaxf((m - mus[n]) * invs[n] * g1[n] + bb1[n], 0.f);
    }
#pragma unroll
    for (int o = 0; o < 16; o++) {
        float a = b3[o];
#pragma unroll
        for (int n = 0; n < 16; n++) a = fmaf(w3[o * 16 + n], r[n], a);
        g_g2[(size_t)(b * 16 + o) * HWC + hw] = a;
        float s = wred(a), q = wred(a * a);
        if ((t & 31) == 0) { atomicAdd(&bs_[o], s); atomicAdd(&bq_[o], q); }
    }
    __syncthreads();
    if (t < 16) { atomicAdd(&g_in2s[b * 16 + t], bs_[t]); atomicAdd(&g_in2q[b * 16 + t], bq_[t]); }
}

// ---------------- 11: IN2 stats finalize ----------------
__global__ void k_in2fin() {
    int i = threadIdx.x;
    float mu = g_in2s[i] / 9216.f;
    float var = g_in2q[i] / 9216.f - mu * mu;
    g_in2stat[2 * i] = mu; g_in2stat[2 * i + 1] = rsqrtf(var + EPSN);
}

// ---------------- 12: IN2+ReLU+1x1(16->3)+sigmoid -> rec ----------------
__global__ void k_rec(const float* __restrict__ in2g, const float* __restrict__ in2b,
                      const float* __restrict__ c4w, const float* __restrict__ c4b,
                      float* __restrict__ out) {
    int b = blockIdx.y; int hw = blockIdx.x * 256 + threadIdx.x; int t = threadIdx.x;
    __shared__ float w4[48], mus[16], invs[16], g2[16], bb2[16];
    if (t < 48) w4[t] = c4w[t];
    if (t < 16) {
        int bo = b * 16 + t;
        mus[t] = g_in2stat[2 * bo]; invs[t] = g_in2stat[2 * bo + 1];
        g2[t] = in2g[t]; bb2[t] = in2b[t];
    }
    __syncthreads();
    float x[16];
#pragma unroll
    for (int o = 0; o < 16; o++) {
        float v = g_g2[(size_t)(b * 16 + o) * HWC + hw];
        x[o] = fmaxf((v - mus[o]) * invs[o] * g2[o] + bb2[o], 0.f);
    }
#pragma unroll
    for (int o2 = 0; o2 < 3; o2++) {
        float a = c4b[o2];
#pragma unroll
        for (int o = 0; o < 16; o++) a = fmaf(w4[o2 * 16 + o], x[o], a);
        out[(size_t)(b * 3 + o2) * HWC + hw] = 1.f / (1.f + expf(-a));
    }
}

// ---------------- 13: op_out = op[bnc] * msk[bn,hw] (float4) ----------------
__global__ void k_opout(const float* __restrict__ msk, float* __restrict__ out) {
    int bn = blockIdx.y; int i4 = blockIdx.x * 256 + threadIdx.x;   // 0..2303
    __shared__ float ops[64];
    if (threadIdx.x < 64) ops[threadIdx.x] = g_op[bn * 64 + threadIdx.x];
    __syncthreads();
    float4 m4 = ((const float4*)(msk + (size_t)bn * HWC))[i4];
    float* ob = out + (size_t)bn * 64 * HWC;
#pragma unroll 8
    for (int c = 0; c < 64; c++) {
        float s = ops[c];
        float4 r; r.x = s * m4.x; r.y = s * m4.y; r.z = s * m4.z; r.w = s * m4.w;
        ((float4*)(ob + (size_t)c * HWC))[i4] = r;
    }
}

// ---------------- launch ----------------
extern "C" void kernel_launch(void* const* d_in, const int* in_sizes, int n_in,
                              void* d_out, int out_size) {
    const float* sr   = (const float*)d_in[0];
    const float* tg   = (const float*)d_in[1];
    const float* ww   = (const float*)d_in[2];
    const float* wb   = (const float*)d_in[3];
    const float* gn1g = (const float*)d_in[4];
    const float* gn1b = (const float*)d_in[5];
    const float* c1w  = (const float*)d_in[6];
    const float* c1b  = (const float*)d_in[7];
    const float* gn2g = (const float*)d_in[8];
    const float* gn2b = (const float*)d_in[9];
    const float* c2w  = (const float*)d_in[10];
    const float* c2b  = (const float*)d_in[11];
    const float* in1g = (const float*)d_in[12];
    const float* in1b = (const float*)d_in[13];
    const float* c3w  = (const float*)d_in[14];
    const float* c3b  = (const float*)d_in[15];
    const float* in2g = (const float*)d_in[16];
    const float* in2b = (const float*)d_in[17];
    const float* c4w  = (const float*)d_in[18];
    const float* c4b  = (const float*)d_in[19];
    float* out = (float*)d_out;
    float* out_msk  = out + 75497472;
    float* out_rec  = out + 76677120;
    float* out_loss = out + 76898304;
    float* out_cof  = out + 76898305;

    k_wprep<<<144, 256>>>(c1w, out_loss);
    k_colsum<<<512, 256>>>(sr, tg);
    k_opu<<<128, 64>>>(ww, wb, 1);
    for (int it = 0; it < 3; it++) {
        k_logits<<<dim3(36, 8), 256>>>(sr);
        k_red<<<1, 128>>>();
        k_v<<<dim3(16, 8), 256>>>(sr, it == 2 ? out_cof : (float*)nullptr);
        if (it < 2) k_opu<<<128, 64>>>(ww, wb, 0);
        else        k_opfin<<<128, 64>>>(ww, wb, gn1g, gn1b);
    }
    k_conv1<<<dim3(6, 6, 128), 256>>>(tg, c1b);
    k_gn2fin<<<128, 64>>>(gn2g, gn2b);
    k_conv2<<<dim3(6, 6, 128), 256>>>(c2w, c2b, out_msk);
    k_msk_stats<<<128, 256>>>(out_msk, out_loss);
    k_gen1<<<dim3(36, 8), 256>>>(out_msk, in1g, in1b, c3w, c3b);
    k_in2fin<<<1, 128>>>();
    k_rec<<<dim3(36, 8), 256>>>(in2g, in2b, c4w, c4b, out_rec);
    k_opout<<<dim3(9, 128), 256>>>(out_msk, out);
}